// round 5
// baseline (speedup 1.0000x reference)
#include <cuda_runtime.h>
#include <math.h>

// ---------------------------------------------------------------------------
// JointEdgeDiceLoss, single kernel, TWO streaming passes (dice, then BCE):
//   region = soft-dice over softmax(segin, C=4) vs one-hot(segmask)
//   edge   = class-balanced BCE-with-logits(edgein, edgemask), t in {0,1}
// Shapes: segin [2,4,96,160,160] f32; edgein/segmask/edgemask [2,1,96,160,160].
// Output: float[2] = {region_loss, edge_loss}.
//
// Register accumulators -> warp/block reduce -> per-block partial in
// __device__ global -> last-block-ticket final reduction in double.
// Deterministic, graph-capturable, allocation-free.
// ---------------------------------------------------------------------------

#define NBLK 1184
#define NTHR 256
#define NQ   16
// partial layout:
//  0..3  : sum of softmax probs per class
//  4..7  : intersect (prob at target class) per class
//  8..10 : one-hot counts classes 0..2  (class 3 = V - c0 - c1 - c2)
//  11    : unused
//  12    : sum of bce over positives (b where t==1)
//  13    : sum of bce over all voxels
//  14    : positive count
//  15    : unused

__device__ float g_part[NBLK][NQ];
__device__ int   g_ticket;          // zero-init at load; reset by last block

__device__ __forceinline__ float frcp_fast(float x) {
    float r;
    asm("rcp.approx.f32 %0, %1;" : "=f"(r) : "f"(x));
    return r;
}

__global__ __launch_bounds__(NTHR) void loss_kernel(
    const float* __restrict__ segin,
    const float* __restrict__ edgein,
    const int*   __restrict__ segmask,
    const int*   __restrict__ edgemask,
    float*       __restrict__ out,
    int V4,     // total voxels / 4
    int DHW)    // d*h*w (channel stride inside one sample)
{
    const int tid    = blockIdx.x * NTHR + threadIdx.x;
    const int stride = gridDim.x * NTHR;
    const int skip   = 3 * DHW;     // extra channel offset for sample 1

    // ---------------- pass 1: dice ----------------
    float s0 = 0.f, s1 = 0.f, s2 = 0.f, s3 = 0.f;     // prob sums per class
    float i0 = 0.f, i1 = 0.f, i2 = 0.f, i3 = 0.f;     // intersect per class
    int   cpk = 0;                                    // packed class counts (8b each)

    for (int j = tid; j < V4; j += stride) {
        const int v = j << 2;
        const float* base = segin + v + ((v >= DHW) ? skip : 0);

        const float4 x0 = *reinterpret_cast<const float4*>(base);
        const float4 x1 = *reinterpret_cast<const float4*>(base + DHW);
        const float4 x2 = *reinterpret_cast<const float4*>(base + 2 * DHW);
        const float4 x3 = *reinterpret_cast<const float4*>(base + 3 * DHW);
        const int4   tv = *reinterpret_cast<const int4*>(segmask + v);

#define DICE_LANE(f) do {                                                   \
        const float e0 = __expf(x0.f), e1 = __expf(x1.f);                   \
        const float e2 = __expf(x2.f), e3 = __expf(x3.f);                   \
        const float inv = frcp_fast((e0 + e1) + (e2 + e3));                 \
        const float p0 = e0 * inv, p1 = e1 * inv;                           \
        const float p2 = e2 * inv, p3 = e3 * inv;                           \
        const int   tt = tv.f;                                              \
        s0 += p0; s1 += p1; s2 += p2; s3 += p3;                             \
        i0 += (tt == 0) ? p0 : 0.0f;                                        \
        i1 += (tt == 1) ? p1 : 0.0f;                                        \
        i2 += (tt == 2) ? p2 : 0.0f;                                        \
        i3 += (tt == 3) ? p3 : 0.0f;                                        \
        cpk += 1 << (tt << 3);                                              \
    } while (0)

        DICE_LANE(x);
        DICE_LANE(y);
        DICE_LANE(z);
        DICE_LANE(w);
#undef DICE_LANE
    }

    // ---------------- pass 2: bce ----------------
    float bpos = 0.f, ball = 0.f;
    int   npos = 0;

    for (int j = tid; j < V4; j += stride) {
        const int v = j << 2;
        const float4 xv = *reinterpret_cast<const float4*>(edgein + v);
        const int4   tv = *reinterpret_cast<const int4*>(edgemask + v);

#define BCE_LANE(f) do {                                                    \
        const float x  = xv.f;                                              \
        const int   tt = tv.f;                                              \
        const float b  = fmaxf(x, 0.0f) - x * (float)tt                     \
                         + __logf(1.0f + __expf(-fabsf(x)));                \
        bpos += tt ? b : 0.0f;                                              \
        ball += b;                                                          \
        npos += tt;                                                         \
    } while (0)

        BCE_LANE(x);
        BCE_LANE(y);
        BCE_LANE(z);
        BCE_LANE(w);
#undef BCE_LANE
    }

    // ---------------- unpack + block reduction ----------------
    float acc[NQ];
    acc[0] = s0; acc[1] = s1; acc[2] = s2; acc[3] = s3;
    acc[4] = i0; acc[5] = i1; acc[6] = i2; acc[7] = i3;
    acc[8]  = (float)( cpk        & 0xFF);
    acc[9]  = (float)((cpk >>  8) & 0xFF);
    acc[10] = (float)((cpk >> 16) & 0xFF);
    acc[11] = 0.0f;
    acc[12] = bpos;
    acc[13] = ball;
    acc[14] = (float)npos;
    acc[15] = 0.0f;

#pragma unroll
    for (int off = 16; off > 0; off >>= 1) {
#pragma unroll
        for (int q = 0; q < NQ; q++)
            acc[q] += __shfl_down_sync(0xffffffffu, acc[q], off);
    }

    __shared__ float sh[NTHR / 32][NQ];
    const int warp = threadIdx.x >> 5;
    const int lane = threadIdx.x & 31;
    if (lane == 0) {
#pragma unroll
        for (int q = 0; q < NQ; q++) sh[warp][q] = acc[q];
    }
    __syncthreads();
    if (threadIdx.x < NQ) {
        float s = 0.0f;
#pragma unroll
        for (int w = 0; w < NTHR / 32; w++) s += sh[w][threadIdx.x];
        g_part[blockIdx.x][threadIdx.x] = s;
    }

    // ---------------- last-block final reduction ----------------
    __shared__ bool is_last;
    __syncthreads();                 // partial stores done block-wide
    if (threadIdx.x == 0) {
        __threadfence();             // publish partials before ticket
        const int t = atomicAdd(&g_ticket, 1);
        is_last = (t == (int)gridDim.x - 1);
    }
    __syncthreads();
    if (!is_last) return;

    __threadfence();                 // acquire: see all blocks' partials

    const int q     = threadIdx.x & 15;
    const int chunk = threadIdx.x >> 4;
    double s = 0.0;
    for (int b = chunk; b < NBLK; b += 16)
        s += (double)__ldcg(&g_part[b][q]);

    __shared__ double shd[16][16];
    shd[chunk][q] = s;
    __syncthreads();

    if (threadIdx.x == 0) {
        double Q[NQ];
#pragma unroll
        for (int qq = 0; qq < NQ; qq++) {
            double t = 0.0;
#pragma unroll
            for (int c = 0; c < 16; c++) t += shd[c][qq];
            Q[qq] = t;
        }

        const double V = 4.0 * (double)V4;

        const double SMOOTH = 1e-5;
        const double cnt[4] = { Q[8], Q[9], Q[10], V - Q[8] - Q[9] - Q[10] };
        double dice_sum = 0.0;
#pragma unroll
        for (int c = 0; c < 4; c++) {
            const double I     = Q[4 + c];
            const double denom = Q[c] + cnt[c];
            dice_sum += (2.0 * I + SMOOTH) / (denom + SMOOTH);
        }
        const double region = 1.0 - dice_sum * 0.25;

        const double pos    = Q[14];
        const double neg    = V - pos;
        const double posbce = Q[12];
        const double negbce = Q[13] - Q[12];
        // weights: pos voxels get neg/V, neg voxels get pos/V; mean over V
        const double edge = (neg * posbce + pos * negbce) / (V * V);

        out[0] = (float)region;
        out[1] = (float)edge;

        g_ticket = 0;                // reset for next (graph-replayed) launch
    }
}

extern "C" void kernel_launch(void* const* d_in, const int* in_sizes, int n_in,
                              void* d_out, int out_size)
{
    const float* segin    = (const float*)d_in[0];
    const float* edgein   = (const float*)d_in[1];
    const int*   segmask  = (const int*)d_in[2];
    const int*   edgemask = (const int*)d_in[3];
    float* out = (float*)d_out;

    const int V   = in_sizes[1];   // n*d*h*w (edgein element count)
    const int V4  = V / 4;
    const int N   = 2;             // fixed batch
    const int DHW = V / N;

    loss_kernel<<<NBLK, NTHR>>>(segin, edgein, segmask, edgemask, out, V4, DHW);
}

// round 6
// speedup vs baseline: 1.1670x; 1.1670x over previous
#include <cuda_runtime.h>
#include <math.h>

// ---------------------------------------------------------------------------
// JointEdgeDiceLoss, single kernel, two streaming passes (dice, then BCE):
//   region = soft-dice over softmax(segin, C=4) vs one-hot(segmask)
//   edge   = class-balanced BCE-with-logits(edgein, edgemask), t in {0,1}
// Shapes: segin [2,4,96,160,160] f32; edgein/segmask/edgemask [2,1,96,160,160].
// Output: float[2] = {region_loss, edge_loss}.
//
// Persistent single-wave grid (148 SMs x 5 blocks), unroll-2 grid-stride,
// register accumulators -> warp/block reduce -> per-block partial ->
// last-block-ticket final reduction in double. Deterministic,
// graph-capturable, allocation-free.
// ---------------------------------------------------------------------------

#define NBLK 740       // 148 SMs * 5 resident blocks: exactly one full wave
#define NTHR 256
#define NQ   16
// partial layout:
//  0..2  : sum of softmax probs classes 0..2 (class 3 = V - s0 - s1 - s2)
//  3     : unused
//  4..7  : intersect (prob at target class) per class
//  8..10 : one-hot counts classes 0..2  (class 3 = V - c0 - c1 - c2)
//  11    : unused
//  12    : sum of bce over positives (b where t==1)
//  13    : sum of bce over all voxels
//  14    : positive count
//  15    : unused

__device__ float g_part[NBLK][NQ];
__device__ int   g_ticket;          // zero-init at load; reset by last block

__device__ __forceinline__ float frcp_fast(float x) {
    float r;
    asm("rcp.approx.f32 %0, %1;" : "=f"(r) : "f"(x));
    return r;
}

__global__ __launch_bounds__(NTHR, 5) void loss_kernel(
    const float* __restrict__ segin,
    const float* __restrict__ edgein,
    const int*   __restrict__ segmask,
    const int*   __restrict__ edgemask,
    float*       __restrict__ out,
    int V4,     // total voxels / 4
    int DHW)    // d*h*w (channel stride inside one sample)
{
    const int tid    = blockIdx.x * NTHR + threadIdx.x;
    const int stride = gridDim.x * NTHR;
    const int skip   = 3 * DHW;     // extra channel offset for sample 1

    // ---------------- pass 1: dice ----------------
    float s0 = 0.f, s1 = 0.f, s2 = 0.f;               // prob sums classes 0..2
    float i0 = 0.f, i1 = 0.f, i2 = 0.f, i3 = 0.f;     // intersect per class
    int   cpk = 0;                                    // packed class counts (8b)

#pragma unroll 2
    for (int j = tid; j < V4; j += stride) {
        const int v = j << 2;
        const float* base = segin + v + ((v >= DHW) ? skip : 0);

        const float4 x0 = *reinterpret_cast<const float4*>(base);
        const float4 x1 = *reinterpret_cast<const float4*>(base + DHW);
        const float4 x2 = *reinterpret_cast<const float4*>(base + 2 * DHW);
        const float4 x3 = *reinterpret_cast<const float4*>(base + 3 * DHW);
        const int4   tv = *reinterpret_cast<const int4*>(segmask + v);

#define DICE_LANE(f) do {                                                   \
        const float e0 = __expf(x0.f), e1 = __expf(x1.f);                   \
        const float e2 = __expf(x2.f), e3 = __expf(x3.f);                   \
        const float inv = frcp_fast((e0 + e1) + (e2 + e3));                 \
        const float p0 = e0 * inv, p1 = e1 * inv;                           \
        const float p2 = e2 * inv, p3 = e3 * inv;                           \
        const int   tt = tv.f;                                              \
        s0 += p0; s1 += p1; s2 += p2;                                       \
        i0 += (tt == 0) ? p0 : 0.0f;                                        \
        i1 += (tt == 1) ? p1 : 0.0f;                                        \
        i2 += (tt == 2) ? p2 : 0.0f;                                        \
        i3 += (tt == 3) ? p3 : 0.0f;                                        \
        cpk += 1 << (tt << 3);                                              \
    } while (0)

        DICE_LANE(x);
        DICE_LANE(y);
        DICE_LANE(z);
        DICE_LANE(w);
#undef DICE_LANE
    }

    // ---------------- pass 2: bce ----------------
    float bpos = 0.f, ball = 0.f;
    int   npos = 0;

#pragma unroll 2
    for (int j = tid; j < V4; j += stride) {
        const int v = j << 2;
        const float4 xv = *reinterpret_cast<const float4*>(edgein + v);
        const int4   tv = *reinterpret_cast<const int4*>(edgemask + v);

#define BCE_LANE(f) do {                                                    \
        const float x  = xv.f;                                              \
        const int   tt = tv.f;                                              \
        const float b  = fmaxf(x, 0.0f) - x * (float)tt                     \
                         + __logf(1.0f + __expf(-fabsf(x)));                \
        bpos += tt ? b : 0.0f;                                              \
        ball += b;                                                          \
        npos += tt;                                                         \
    } while (0)

        BCE_LANE(x);
        BCE_LANE(y);
        BCE_LANE(z);
        BCE_LANE(w);
#undef BCE_LANE
    }

    // ---------------- unpack + block reduction ----------------
    float acc[NQ];
    acc[0] = s0; acc[1] = s1; acc[2] = s2; acc[3] = 0.0f;
    acc[4] = i0; acc[5] = i1; acc[6] = i2; acc[7] = i3;
    acc[8]  = (float)( cpk        & 0xFF);
    acc[9]  = (float)((cpk >>  8) & 0xFF);
    acc[10] = (float)((cpk >> 16) & 0xFF);
    acc[11] = 0.0f;
    acc[12] = bpos;
    acc[13] = ball;
    acc[14] = (float)npos;
    acc[15] = 0.0f;

#pragma unroll
    for (int off = 16; off > 0; off >>= 1) {
#pragma unroll
        for (int q = 0; q < NQ; q++)
            acc[q] += __shfl_down_sync(0xffffffffu, acc[q], off);
    }

    __shared__ float sh[NTHR / 32][NQ];
    const int warp = threadIdx.x >> 5;
    const int lane = threadIdx.x & 31;
    if (lane == 0) {
#pragma unroll
        for (int q = 0; q < NQ; q++) sh[warp][q] = acc[q];
    }
    __syncthreads();
    if (threadIdx.x < NQ) {
        float s = 0.0f;
#pragma unroll
        for (int w = 0; w < NTHR / 32; w++) s += sh[w][threadIdx.x];
        g_part[blockIdx.x][threadIdx.x] = s;
    }

    // ---------------- last-block final reduction ----------------
    __shared__ bool is_last;
    __syncthreads();                 // partial stores done block-wide
    if (threadIdx.x == 0) {
        __threadfence();             // publish partials before ticket
        const int t = atomicAdd(&g_ticket, 1);
        is_last = (t == (int)gridDim.x - 1);
    }
    __syncthreads();
    if (!is_last) return;

    __threadfence();                 // acquire: see all blocks' partials

    const int q     = threadIdx.x & 15;
    const int chunk = threadIdx.x >> 4;
    double s = 0.0;
    for (int b = chunk; b < NBLK; b += 16)
        s += (double)__ldcg(&g_part[b][q]);

    __shared__ double shd[16][16];
    shd[chunk][q] = s;
    __syncthreads();

    if (threadIdx.x == 0) {
        double Q[NQ];
#pragma unroll
        for (int qq = 0; qq < NQ; qq++) {
            double t = 0.0;
#pragma unroll
            for (int c = 0; c < 16; c++) t += shd[c][qq];
            Q[qq] = t;
        }

        const double V = 4.0 * (double)V4;

        const double SMOOTH = 1e-5;
        const double psum[4] = { Q[0], Q[1], Q[2], V - Q[0] - Q[1] - Q[2] };
        const double cnt[4]  = { Q[8], Q[9], Q[10], V - Q[8] - Q[9] - Q[10] };
        double dice_sum = 0.0;
#pragma unroll
        for (int c = 0; c < 4; c++) {
            const double I     = Q[4 + c];
            const double denom = psum[c] + cnt[c];
            dice_sum += (2.0 * I + SMOOTH) / (denom + SMOOTH);
        }
        const double region = 1.0 - dice_sum * 0.25;

        const double pos    = Q[14];
        const double neg    = V - pos;
        const double posbce = Q[12];
        const double negbce = Q[13] - Q[12];
        // weights: pos voxels get neg/V, neg voxels get pos/V; mean over V
        const double edge = (neg * posbce + pos * negbce) / (V * V);

        out[0] = (float)region;
        out[1] = (float)edge;

        g_ticket = 0;                // reset for next (graph-replayed) launch
    }
}

extern "C" void kernel_launch(void* const* d_in, const int* in_sizes, int n_in,
                              void* d_out, int out_size)
{
    const float* segin    = (const float*)d_in[0];
    const float* edgein   = (const float*)d_in[1];
    const int*   segmask  = (const int*)d_in[2];
    const int*   edgemask = (const int*)d_in[3];
    float* out = (float*)d_out;

    const int V   = in_sizes[1];   // n*d*h*w (edgein element count)
    const int V4  = V / 4;
    const int N   = 2;             // fixed batch
    const int DHW = V / N;

    loss_kernel<<<NBLK, NTHR>>>(segin, edgein, segmask, edgemask, out, V4, DHW);
}